// round 15
// baseline (speedup 1.0000x reference)
#include <cuda_runtime.h>

#define BB 4
#define NT 256
#define NZ 384
#define NXX 384
#define NREC 128
#define DTc 0.001f
#define DHc 10.0f

#define NBLK 256
#define BLK_PER_B (NBLK / BB)      // 64 blocks per batch
#define ROWS 6                     // owned rows per block
#define NPAIR (NXX / 2)            // 192 column pairs
#define NGRP 2                     // row groups (both are boundary groups)
#define RPT 3                      // rows per thread
#define NTHR (NPAIR * NGRP)        // 384 threads

// Packed halo word: hi32 = step counter (t+1 when u(t) published), lo32 = value.
// Single-word atomicity of each 64-bit half IS the synchronization; WAR on slot
// reuse is protected by the publish->consume data-dependency chain.
__device__ __align__(16) unsigned long long d_pack[2][NBLK][2][NXX];
#define SLOT_OFF (NBLK * 2 * NXX)   // u64 elements between slot 0 and slot 1

__global__ void zero_kernel() {
    const int n = 2 * NBLK * 2 * NXX;
    for (int i = blockIdx.x * blockDim.x + threadIdx.x; i < n;
         i += gridDim.x * blockDim.x)
        ((unsigned long long*)d_pack)[i] = 0ull;
}

__device__ __forceinline__ unsigned long long ld_vol_u64(
        const unsigned long long* p) {
    unsigned long long v;
    asm volatile("ld.volatile.global.u64 %0, [%1];" : "=l"(v) : "l"(p));
    return v;
}
__device__ __forceinline__ void st_vol_u64x2(unsigned long long* p,
                                             unsigned long long a,
                                             unsigned long long b) {
    asm volatile("st.volatile.global.v2.u64 [%0], {%1, %2};"
                 :: "l"(p), "l"(a), "l"(b));
}
__device__ __forceinline__ void ld_vol_u64x2(const unsigned long long* p,
                                             unsigned long long& a,
                                             unsigned long long& b) {
    asm volatile("ld.volatile.global.v2.u64 {%0, %1}, [%2];"
                 : "=l"(a), "=l"(b) : "l"(p));
}

__global__ __launch_bounds__(NTHR, 2) void wave_kernel(
    const float* __restrict__ xsrc,   // [B, NT]
    const float* __restrict__ vp,     // [NZ, NX]
    const int*   __restrict__ src_y,
    const int*   __restrict__ src_x,
    const int*   __restrict__ rec_y,
    const int*   __restrict__ rec_x,
    float*       __restrict__ out)    // [NT, B, NREC]
{
    __shared__ float sb0[ROWS * NXX];
    __shared__ float sb1[ROWS * NXX];
    __shared__ float sxs[NT];               // staged source trace for this batch

    const int tid = threadIdx.x;
    const int p   = tid % NPAIR;            // column pair
    const int g   = tid / NPAIR;            // row group (warp-uniform: 6 warps/grp)
    const int x0  = 2 * p;
    const int x1  = x0 + 1;
    const int blk = blockIdx.x;
    const int b   = blk / BLK_PER_B;
    const int bib = blk % BLK_PER_B;
    const int z0  = bib * ROWS;
    const int rowbase = g * RPT;
    const float inv_dh2 = 1.0f / (DHc * DHc);

    const int topBlk = (bib > 0) ? blk - 1 : -1;
    const int botBlk = (bib < BLK_PER_B - 1) ? blk + 1 : -1;
    const bool isTop = (g == 0);
    const int  nb    = isTop ? topBlk : botBlk;       // outward neighbor
    const bool hasNb = (nb >= 0);
    const int  side  = isTop ? 0 : 1;

    const int sy = src_y[b];
    const int sx = src_x[b];

    float ucA[RPT], ucB[RPT], pvA[RPT], pvB[RPT], csA[RPT], csB[RPT];
    unsigned smA = 0, smB = 0;              // source masks per column

    // stage the source trace
    for (int i = tid; i < NT; i += NTHR)
        sxs[i] = xsrc[b * NT + i];

#pragma unroll
    for (int k = 0; k < RPT; k++) {
        const int zg = z0 + rowbase + k;
        ucA[k] = 0.0f; ucB[k] = 0.0f;
        pvA[k] = 0.0f; pvB[k] = 0.0f;
        const float cA = vp[zg * NXX + x0] * DTc;
        const float cB = vp[zg * NXX + x1] * DTc;
        const bool zok = (zg > 0 && zg < NZ - 1);
        csA[k] = (zok && x0 > 0)       ? (cA * cA * inv_dh2) : 0.0f;
        csB[k] = (zok && x1 < NXX - 1) ? (cB * cB * inv_dh2) : 0.0f;
        if (zg == sy && x0 == sx) smA |= (1u << k);
        if (zg == sy && x1 == sx) smB |= (1u << k);
        sb0[(rowbase + k) * NXX + x0] = 0.0f;
        sb0[(rowbase + k) * NXX + x1] = 0.0f;
        sb1[(rowbase + k) * NXX + x0] = 0.0f;
        sb1[(rowbase + k) * NXX + x1] = 0.0f;
    }

    int rmine = 0, roff = 0;
    float* outp = out;
    if (tid < NREC) {
        const int ry = rec_y[tid];
        const int rx = rec_x[tid];
        rmine = (ry >= z0 && ry < z0 + ROWS);
        roff  = (ry - z0) * NXX + rx;
        outp  = out + b * NREC + tid;
    }

    const int pbase = rowbase * NXX + x0;
    const int dxl   = (x0 > 0) ? 1 : 0;            // clamped (csc=0 at edges)
    const int dxr   = (x1 < NXX - 1) ? 1 : 0;

    // handshake base pointers, slot 0 (slot 1 = +SLOT_OFF, folded to imm)
    unsigned long long* pubA = &d_pack[0][blk][side][x0];
    const unsigned long long* polA =
        hasNb ? &d_pack[0][nb][side ^ 1][x0] : pubA;

    float hNbA = 0.0f, hNbB = 0.0f;         // neighbor boundary u(t-1)
    unsigned long long specA = 0ull, specB = 0ull;   // in-flight poll results

    __syncthreads();

    // one row of the pair: up/dn explicit, left/right from smem+regs
    #define DO_ROW(k, upA_, upB_, dnA_, dnB_, RBUF, WBUF, xt)                   \
    {                                                                           \
        const int pr = pbase + (k) * NXX;                                       \
        const float uA = ucA[k], uB = ucB[k];                                   \
        const float Lv = RBUF[pr - dxl];                                        \
        const float Rv = RBUF[pr + 1 + dxr];                                    \
        const float lapA = (upA_) + (dnA_) + Lv + uB - 4.0f * uA;               \
        const float lapB = (upB_) + (dnB_) + uA + Rv - 4.0f * uB;               \
        float hA = fmaf(csA[k], lapA, 2.0f * uA - pvA[k]);                      \
        float hB = fmaf(csB[k], lapB, 2.0f * uB - pvB[k]);                      \
        if (smA & (1u << (k))) hA += xt;                                        \
        if (smB & (1u << (k))) hB += xt;                                        \
        pvA[k] = uA; pvB[k] = uB;                                               \
        ucA[k] = hA; ucB[k] = hB;                                               \
        *(float2*)&WBUF[pr] = make_float2(hA, hB);                              \
    }

    // SOFF = slot t&1 (publish / late poll); PSOFF = slot (t-1)&1 (consume).
    #define STEP(T, RBUF, WBUF, SOFF, PSOFF)                                    \
    {                                                                           \
        const int   t  = (T);                                                   \
        const float xt = sxs[t];                                                \
        /* old values (pre-update) needed as vertical neighbors */              \
        const float a0 = ucA[0], b0 = ucB[0];                                   \
        const float a1 = ucA[1], b1 = ucB[1];                                   \
        const float a2 = ucA[2], b2 = ucB[2];                                   \
        /* Phase 0: consume last step's spec = neighbor u(t-1) (post-bar) */    \
        if (hasNb && t > 0) {                                                   \
            unsigned long long vA = specA, vB = specB;                          \
            while ((int)(vA >> 32) < t) vA = ld_vol_u64(polA + (PSOFF));        \
            while ((int)(vB >> 32) < t) vB = ld_vol_u64(polA + (PSOFF) + 1);    \
            hNbA = __uint_as_float((unsigned)vA);                               \
            hNbB = __uint_as_float((unsigned)vB);                               \
        }                                                                       \
        /* Phase 1: boundary row first, publish immediately (one STG.128) */    \
        if (isTop) {                                                            \
            DO_ROW(0, hNbA, hNbB, a1, b1, RBUF, WBUF, xt);                      \
            if (hasNb) {                                                        \
                const unsigned long long hi =                                   \
                    (unsigned long long)(unsigned)(t + 1) << 32;                \
                st_vol_u64x2(pubA + (SOFF), hi | __float_as_uint(ucA[0]),       \
                                            hi | __float_as_uint(ucB[0]));      \
            }                                                                   \
        } else {                                                                \
            DO_ROW(2, a1, b1, hNbA, hNbB, RBUF, WBUF, xt);                      \
            if (hasNb) {                                                        \
                const unsigned long long hi =                                   \
                    (unsigned long long)(unsigned)(t + 1) << 32;                \
                st_vol_u64x2(pubA + (SOFF), hi | __float_as_uint(ucA[2]),       \
                                            hi | __float_as_uint(ucB[2]));      \
            }                                                                   \
        }                                                                       \
        /* receiver gather for step t-1 (off the publish path) */               \
        if (t > 0 && rmine) { outp[(t - 1) * (BB * NREC)] = RBUF[roff]; }       \
        /* Phase 2: remaining rows */                                           \
        if (isTop) {                                                            \
            DO_ROW(1, a0, b0, a2, b2, RBUF, WBUF, xt);                          \
            const float2 dn = *(const float2*)&RBUF[pbase + RPT * NXX];         \
            DO_ROW(2, a1, b1, dn.x, dn.y, RBUF, WBUF, xt);                      \
        } else {                                                                \
            const float2 up = *(const float2*)&RBUF[pbase - NXX];               \
            DO_ROW(0, up.x, up.y, a1, b1, RBUF, WBUF, xt);                      \
            DO_ROW(1, a0, b0, a2, b2, RBUF, WBUF, xt);                          \
        }                                                                       \
        /* Phase 3: late poll for neighbor u(t); consumed NEXT step */          \
        if (hasNb && t < NT - 1)                                                \
            ld_vol_u64x2(polA + (SOFF), specA, specB);                          \
        __syncthreads();                                                        \
    }

#pragma unroll 1
    for (int tt = 0; tt < NT; tt += 2) {
        STEP(tt,     sb0, sb1, 0, SLOT_OFF)   // even t: publish slot 0
        STEP(tt + 1, sb1, sb0, SLOT_OFF, 0)   // odd  t: publish slot 1
    }
    #undef STEP
    #undef DO_ROW

    // final receiver gather for t = NT-1 (last wbuf = sb0 since NT even)
    if (rmine)
        outp[(NT - 1) * (BB * NREC)] = sb0[roff];
}

extern "C" void kernel_launch(void* const* d_in, const int* in_sizes, int n_in,
                              void* d_out, int out_size)
{
    const float* xsrc  = (const float*)d_in[0];
    const float* vp    = (const float*)d_in[1];
    const int*   src_y = (const int*)d_in[2];
    const int*   src_x = (const int*)d_in[3];
    const int*   rec_y = (const int*)d_in[4];
    const int*   rec_x = (const int*)d_in[5];
    float*       out   = (float*)d_out;

    zero_kernel<<<128, 512>>>();
    wave_kernel<<<NBLK, NTHR>>>(xsrc, vp, src_y, src_x, rec_y, rec_x, out);
}

// round 16
// speedup vs baseline: 1.3838x; 1.3838x over previous
#include <cuda_runtime.h>

#define BB 4
#define NT 256
#define NZ 384
#define NXX 384
#define NREC 128
#define DTc 0.001f
#define DHc 10.0f

#define NBLK 128
#define BLK_PER_B (NBLK / BB)      // 32 blocks per batch
#define ROWS 12                    // owned rows per block
#define NPAIR (NXX / 2)            // 192 column pairs
#define NGRP 4                     // row groups
#define RPT 3                      // rows per thread
#define NTHR (NPAIR * NGRP)        // 768 threads

// Packed halo word: hi32 = step counter (t+1 when u(t) published), lo32 = value.
// Single-word atomicity of each 64-bit half IS the synchronization; WAR on slot
// reuse is protected by the publish->consume data-dependency chain.
__device__ __align__(16) unsigned long long d_pack[2][NBLK][2][NXX];
#define SLOT_OFF (NBLK * 2 * NXX)   // u64 elements between slot 0 and slot 1

__global__ void zero_kernel() {
    const int n = 2 * NBLK * 2 * NXX;
    for (int i = blockIdx.x * blockDim.x + threadIdx.x; i < n;
         i += gridDim.x * blockDim.x)
        ((unsigned long long*)d_pack)[i] = 0ull;
}

__device__ __forceinline__ unsigned long long ld_vol_u64(
        const unsigned long long* p) {
    unsigned long long v;
    asm volatile("ld.volatile.global.u64 %0, [%1];" : "=l"(v) : "l"(p));
    return v;
}
__device__ __forceinline__ void st_vol_u64x2(unsigned long long* p,
                                             unsigned long long a,
                                             unsigned long long b) {
    asm volatile("st.volatile.global.v2.u64 [%0], {%1, %2};"
                 :: "l"(p), "l"(a), "l"(b));
}
__device__ __forceinline__ void ld_vol_u64x2(const unsigned long long* p,
                                             unsigned long long& a,
                                             unsigned long long& b) {
    asm volatile("ld.volatile.global.v2.u64 {%0, %1}, [%2];"
                 : "=l"(a), "=l"(b) : "l"(p));
}

__global__ __launch_bounds__(NTHR, 1) void wave_kernel(
    const float* __restrict__ xsrc,   // [B, NT]
    const float* __restrict__ vp,     // [NZ, NX]
    const int*   __restrict__ src_y,
    const int*   __restrict__ src_x,
    const int*   __restrict__ rec_y,
    const int*   __restrict__ rec_x,
    float*       __restrict__ out)    // [NT, B, NREC]
{
    __shared__ float sb0[ROWS * NXX];
    __shared__ float sb1[ROWS * NXX];
    __shared__ float sxs[NT];               // staged source trace for this batch

    const int tid = threadIdx.x;
    const int p   = tid % NPAIR;            // column pair
    const int g   = tid / NPAIR;            // row group (warp-uniform: 6 warps/grp)
    const int x0  = 2 * p;
    const int x1  = x0 + 1;
    const int blk = blockIdx.x;
    const int b   = blk / BLK_PER_B;
    const int bib = blk % BLK_PER_B;
    const int z0  = bib * ROWS;
    const int rowbase = g * RPT;
    const float inv_dh2 = 1.0f / (DHc * DHc);

    const int topBlk = (bib > 0) ? blk - 1 : -1;
    const int botBlk = (bib < BLK_PER_B - 1) ? blk + 1 : -1;
    const bool isTop = (g == 0);
    const bool isBot = (g == NGRP - 1);
    const int  nb    = isTop ? topBlk : (isBot ? botBlk : -1);
    const bool hasNb = (nb >= 0);
    const int  side  = isTop ? 0 : 1;

    const int sy = src_y[b];
    const int sx = src_x[b];

    float ucA[RPT], ucB[RPT], pvA[RPT], pvB[RPT], csA[RPT], csB[RPT];
    unsigned smA = 0, smB = 0;              // source masks per column

    // stage the source trace
    for (int i = tid; i < NT; i += NTHR)
        sxs[i] = xsrc[b * NT + i];

#pragma unroll
    for (int k = 0; k < RPT; k++) {
        const int zg = z0 + rowbase + k;
        ucA[k] = 0.0f; ucB[k] = 0.0f;
        pvA[k] = 0.0f; pvB[k] = 0.0f;
        const float cA = vp[zg * NXX + x0] * DTc;
        const float cB = vp[zg * NXX + x1] * DTc;
        const bool zok = (zg > 0 && zg < NZ - 1);
        csA[k] = (zok && x0 > 0)       ? (cA * cA * inv_dh2) : 0.0f;
        csB[k] = (zok && x1 < NXX - 1) ? (cB * cB * inv_dh2) : 0.0f;
        if (zg == sy && x0 == sx) smA |= (1u << k);
        if (zg == sy && x1 == sx) smB |= (1u << k);
        sb0[(rowbase + k) * NXX + x0] = 0.0f;
        sb0[(rowbase + k) * NXX + x1] = 0.0f;
        sb1[(rowbase + k) * NXX + x0] = 0.0f;
        sb1[(rowbase + k) * NXX + x1] = 0.0f;
    }

    int rmine = 0, roff = 0;
    float* outp = out;
    if (tid < NREC) {
        const int ry = rec_y[tid];
        const int rx = rec_x[tid];
        rmine = (ry >= z0 && ry < z0 + ROWS);
        roff  = (ry - z0) * NXX + rx;
        outp  = out + b * NREC + tid;
    }

    const int pbase = rowbase * NXX + x0;
    // conflict-free horizontal loads: aligned float2 at pr-2 / pr+2, use .y / .x.
    // Edge columns clamp offset to 0; the unused-lane value is finite and the
    // corresponding csc is 0, so it never affects results.
    const int ofsL = (x0 > 0) ? -2 : 0;
    const int ofsR = (x1 < NXX - 1) ? 2 : 0;

    // handshake base pointers, slot 0 (slot 1 = +SLOT_OFF, folded to imm)
    unsigned long long* pubA = &d_pack[0][blk][side][x0];
    const unsigned long long* polA =
        hasNb ? &d_pack[0][nb][side ^ 1][x0] : pubA;

    float hNbA = 0.0f, hNbB = 0.0f;         // neighbor boundary u(t-1)
    unsigned long long specA = 0ull, specB = 0ull;   // in-flight poll results

    __syncthreads();

    // one row of the pair: up/dn explicit, left/right via LDS.64 (conflict-free)
    #define DO_ROW(k, upA_, upB_, dnA_, dnB_, RBUF, WBUF, xt)                   \
    {                                                                           \
        const int pr = pbase + (k) * NXX;                                       \
        const float uA = ucA[k], uB = ucB[k];                                   \
        const float2 L2 = *(const float2*)&RBUF[pr + ofsL];                     \
        const float2 R2 = *(const float2*)&RBUF[pr + ofsR];                     \
        const float lapA = (upA_) + (dnA_) + L2.y + uB - 4.0f * uA;             \
        const float lapB = (upB_) + (dnB_) + uA + R2.x - 4.0f * uB;             \
        float hA = fmaf(csA[k], lapA, 2.0f * uA - pvA[k]);                      \
        float hB = fmaf(csB[k], lapB, 2.0f * uB - pvB[k]);                      \
        if (smA & (1u << (k))) hA += xt;                                        \
        if (smB & (1u << (k))) hB += xt;                                        \
        pvA[k] = uA; pvB[k] = uB;                                               \
        ucA[k] = hA; ucB[k] = hB;                                               \
        *(float2*)&WBUF[pr] = make_float2(hA, hB);                              \
    }

    // SOFF = slot t&1 (publish / late poll); PSOFF = slot (t-1)&1 (consume).
    #define STEP(T, RBUF, WBUF, SOFF, PSOFF)                                    \
    {                                                                           \
        const int   t  = (T);                                                   \
        const float xt = sxs[t];                                                \
        /* old values (pre-update) needed as vertical neighbors */              \
        const float a0 = ucA[0], b0 = ucB[0];                                   \
        const float a1 = ucA[1], b1 = ucB[1];                                   \
        const float a2 = ucA[2], b2 = ucB[2];                                   \
        /* Phase 0: consume last step's spec = neighbor u(t-1) (post-bar) */    \
        if (hasNb && t > 0) {                                                   \
            unsigned long long vA = specA, vB = specB;                          \
            while ((int)(vA >> 32) < t) vA = ld_vol_u64(polA + (PSOFF));        \
            while ((int)(vB >> 32) < t) vB = ld_vol_u64(polA + (PSOFF) + 1);    \
            hNbA = __uint_as_float((unsigned)vA);                               \
            hNbB = __uint_as_float((unsigned)vB);                               \
        }                                                                       \
        /* Phase 1: boundary row first, publish immediately (one STG.128) */    \
        if (isTop) {                                                            \
            DO_ROW(0, hNbA, hNbB, a1, b1, RBUF, WBUF, xt);                      \
            if (hasNb) {                                                        \
                const unsigned long long hi =                                   \
                    (unsigned long long)(unsigned)(t + 1) << 32;                \
                st_vol_u64x2(pubA + (SOFF), hi | __float_as_uint(ucA[0]),       \
                                            hi | __float_as_uint(ucB[0]));      \
            }                                                                   \
        } else if (isBot) {                                                     \
            DO_ROW(2, a1, b1, hNbA, hNbB, RBUF, WBUF, xt);                      \
            if (hasNb) {                                                        \
                const unsigned long long hi =                                   \
                    (unsigned long long)(unsigned)(t + 1) << 32;                \
                st_vol_u64x2(pubA + (SOFF), hi | __float_as_uint(ucA[2]),       \
                                            hi | __float_as_uint(ucB[2]));      \
            }                                                                   \
        }                                                                       \
        /* receiver gather for step t-1 (off the publish path) */               \
        if (t > 0 && rmine) { outp[(t - 1) * (BB * NREC)] = RBUF[roff]; }       \
        /* Phase 2: remaining rows */                                           \
        if (isTop) {                                                            \
            DO_ROW(1, a0, b0, a2, b2, RBUF, WBUF, xt);                          \
            const float2 dn = *(const float2*)&RBUF[pbase + RPT * NXX];         \
            DO_ROW(2, a1, b1, dn.x, dn.y, RBUF, WBUF, xt);                      \
        } else if (isBot) {                                                     \
            const float2 up = *(const float2*)&RBUF[pbase - NXX];               \
            DO_ROW(0, up.x, up.y, a1, b1, RBUF, WBUF, xt);                      \
            DO_ROW(1, a0, b0, a2, b2, RBUF, WBUF, xt);                          \
        } else {                                                                \
            const float2 up = *(const float2*)&RBUF[pbase - NXX];               \
            DO_ROW(0, up.x, up.y, a1, b1, RBUF, WBUF, xt);                      \
            DO_ROW(1, a0, b0, a2, b2, RBUF, WBUF, xt);                          \
            const float2 dn = *(const float2*)&RBUF[pbase + RPT * NXX];         \
            DO_ROW(2, a1, b1, dn.x, dn.y, RBUF, WBUF, xt);                      \
        }                                                                       \
        /* Phase 3: late poll for neighbor u(t); consumed NEXT step */          \
        if (hasNb && t < NT - 1)                                                \
            ld_vol_u64x2(polA + (SOFF), specA, specB);                          \
        __syncthreads();                                                        \
    }

#pragma unroll 1
    for (int tt = 0; tt < NT; tt += 2) {
        STEP(tt,     sb0, sb1, 0, SLOT_OFF)   // even t: publish slot 0
        STEP(tt + 1, sb1, sb0, SLOT_OFF, 0)   // odd  t: publish slot 1
    }
    #undef STEP
    #undef DO_ROW

    // final receiver gather for t = NT-1 (last wbuf = sb0 since NT even)
    if (rmine)
        outp[(NT - 1) * (BB * NREC)] = sb0[roff];
}

extern "C" void kernel_launch(void* const* d_in, const int* in_sizes, int n_in,
                              void* d_out, int out_size)
{
    const float* xsrc  = (const float*)d_in[0];
    const float* vp    = (const float*)d_in[1];
    const int*   src_y = (const int*)d_in[2];
    const int*   src_x = (const int*)d_in[3];
    const int*   rec_y = (const int*)d_in[4];
    const int*   rec_x = (const int*)d_in[5];
    float*       out   = (float*)d_out;

    zero_kernel<<<128, 512>>>();
    wave_kernel<<<NBLK, NTHR>>>(xsrc, vp, src_y, src_x, rec_y, rec_x, out);
}